// round 10
// baseline (speedup 1.0000x reference)
#include <cuda_runtime.h>
#include <cuda_bf16.h>
#include <cstdint>

// ---------------- problem constants ----------------
#define BATCH   256
#define NH      12
#define HD      64
#define DIM     768          // NH*HD
#define WIN     14
#define NTOK    196          // WIN*WIN
#define NPAD    256          // padded token count for K/V tiles
#define MTOT    (BATCH*NTOK) // 50176
#define REL     27           // 2*WIN-1

// ---------------- scratch (device globals; no allocation allowed) -------
__device__ float g_q[BATCH*NH*NTOK*HD];                      // fp32, q*0.125
__device__ __nv_bfloat16 g_kH[BATCH*NH*NPAD*HD], g_kL[BATCH*NH*NPAD*HD]; // [b][h][n][d]
__device__ __nv_bfloat16 g_vH[BATCH*NH*HD*NPAD], g_vL[BATCH*NH*HD*NPAD]; // [b][h][d][n]
__device__ __nv_bfloat16 g_xH[MTOT*DIM],  g_xL[MTOT*DIM];    // x split
__device__ __nv_bfloat16 g_wqH[3*DIM*DIM], g_wqL[3*DIM*DIM]; // qkv_w split
__device__ __nv_bfloat16 g_wpH[DIM*DIM],  g_wpL[DIM*DIM];    // proj_w split
__device__ __nv_bfloat16 g_aoH[MTOT*DIM], g_aoL[MTOT*DIM];   // attn out split

// =========================================================================
// helpers
// =========================================================================
// NOTE: no "volatile" — dependencies are fully expressed by the register
// constraints; the compiler is free to interleave MMAs across accumulators
// to break RAW chains.
__device__ __forceinline__ void mma_bf16(float c[4],
                                         uint32_t a0, uint32_t a1, uint32_t a2, uint32_t a3,
                                         uint32_t b0, uint32_t b1)
{
    asm("mma.sync.aligned.m16n8k16.row.col.f32.bf16.bf16.f32 "
        "{%0,%1,%2,%3}, {%4,%5,%6,%7}, {%8,%9}, {%0,%1,%2,%3};"
        : "+f"(c[0]), "+f"(c[1]), "+f"(c[2]), "+f"(c[3])
        : "r"(a0), "r"(a1), "r"(a2), "r"(a3), "r"(b0), "r"(b1));
}

__device__ __forceinline__ void pack_hl(float x0, float x1, uint32_t& hi, uint32_t& lo)
{
    uint32_t h;
    asm("cvt.rn.bf16x2.f32 %0, %1, %2;" : "=r"(h) : "f"(x1), "f"(x0));
    float h0 = __uint_as_float(h << 16);
    float h1 = __uint_as_float(h & 0xFFFF0000u);
    float l0 = x0 - h0;
    float l1 = x1 - h1;
    uint32_t l;
    asm("cvt.rn.bf16x2.f32 %0, %1, %2;" : "=r"(l) : "f"(l1), "f"(l0));
    hi = h; lo = l;
}

__device__ __forceinline__ void cp16(uint32_t dst, const void* src)
{
    asm volatile("cp.async.cg.shared.global [%0], [%1], 16;" :: "r"(dst), "l"(src));
}
#define CP_COMMIT() asm volatile("cp.async.commit_group;")
#define CP_WAIT(n)  asm volatile("cp.async.wait_group %0;" :: "n"(n))

// =========================================================================
// one-shot fp32 -> bf16 hi/lo split kernels
// =========================================================================
template<int WHICH>
__global__ __launch_bounds__(256) void split_kernel(const float* __restrict__ src, int n2)
{
    const int i = blockIdx.x * 256 + threadIdx.x;
    if (i >= n2) return;
    float2 v = ((const float2*)src)[i];
    uint32_t h, l;
    pack_hl(v.x, v.y, h, l);
    uint32_t* H;
    uint32_t* L;
    if (WHICH == 0)      { H = (uint32_t*)g_xH;  L = (uint32_t*)g_xL;  }
    else if (WHICH == 1) { H = (uint32_t*)g_wqH; L = (uint32_t*)g_wqL; }
    else                 { H = (uint32_t*)g_wpH; L = (uint32_t*)g_wpL; }
    H[i] = h;
    L[i] = l;
}

// =========================================================================
// bf16 mma GEMM: reg-prefetch + pre-split operands + term-outer MMA order.
// CTA tile 128x128, BK=32, 256 threads = 8 warps (2M x 4N), warp 64x32.
// =========================================================================
#define KSTR 40                       // bf16 smem row stride

template<int MODE>
__global__ __launch_bounds__(256) void gemm_mma(const float* __restrict__ bias,
                                                float* __restrict__ out)
{
    __shared__ __nv_bfloat16 AsH[128 * KSTR];
    __shared__ __nv_bfloat16 AsL[128 * KSTR];
    __shared__ __nv_bfloat16 BsH[128 * KSTR];
    __shared__ __nv_bfloat16 BsL[128 * KSTR];

    const int tid = threadIdx.x;
    const int m0  = blockIdx.y * 128;
    const int n0  = blockIdx.x * 128;

    const int w    = tid >> 5;
    const int lane = tid & 31;
    const int g    = lane >> 2;
    const int t    = lane & 3;
    const int wm   = (w >> 2) * 64;
    const int wn   = (w & 3) * 32;

    const int lr = tid >> 2;          // 0..63
    const int lc = (tid & 3) * 8;     // bf16 col 0,8,16,24

    const __nv_bfloat16* gAH = (MODE ? g_aoH : g_xH) + (size_t)(m0 + lr) * 768 + lc;
    const __nv_bfloat16* gAL = (MODE ? g_aoL : g_xL) + (size_t)(m0 + lr) * 768 + lc;
    const __nv_bfloat16* gBH = (MODE ? g_wpH : g_wqH) + (size_t)(n0 + lr) * 768 + lc;
    const __nv_bfloat16* gBL = (MODE ? g_wpL : g_wqL) + (size_t)(n0 + lr) * 768 + lc;
    const size_t rstep = (size_t)64 * 768;

    float acc[4][4][4];
#pragma unroll
    for (int i = 0; i < 4; i++)
#pragma unroll
        for (int j = 0; j < 4; j++)
#pragma unroll
            for (int r = 0; r < 4; r++) acc[i][j][r] = 0.f;

    uint4 pah[2], pal[2], pbh[2], pbl[2];
    pah[0] = *(const uint4*)(gAH);          pah[1] = *(const uint4*)(gAH + rstep);
    pal[0] = *(const uint4*)(gAL);          pal[1] = *(const uint4*)(gAL + rstep);
    pbh[0] = *(const uint4*)(gBH);          pbh[1] = *(const uint4*)(gBH + rstep);
    pbl[0] = *(const uint4*)(gBL);          pbl[1] = *(const uint4*)(gBL + rstep);

    for (int k0 = 0; k0 < 768; k0 += 32) {
#pragma unroll
        for (int i = 0; i < 2; i++) {
            const int ro = (lr + i * 64) * KSTR + lc;
            *(uint4*)&AsH[ro] = pah[i];
            *(uint4*)&AsL[ro] = pal[i];
            *(uint4*)&BsH[ro] = pbh[i];
            *(uint4*)&BsL[ro] = pbl[i];
        }
        __syncthreads();

        if (k0 + 32 < 768) {
            const int k1 = k0 + 32;
            pah[0] = *(const uint4*)(gAH + k1);          pah[1] = *(const uint4*)(gAH + k1 + rstep);
            pal[0] = *(const uint4*)(gAL + k1);          pal[1] = *(const uint4*)(gAL + k1 + rstep);
            pbh[0] = *(const uint4*)(gBH + k1);          pbh[1] = *(const uint4*)(gBH + k1 + rstep);
            pbl[0] = *(const uint4*)(gBL + k1);          pbl[1] = *(const uint4*)(gBL + k1 + rstep);
        }

#pragma unroll
        for (int ks = 0; ks < 2; ks++) {
            const int kb = ks * 16 + 2 * t;
            uint32_t ah[4][4], al[4][4], bh[4][2], bl[4][2];
#pragma unroll
            for (int mt = 0; mt < 4; mt++) {
                const int ro = (wm + mt * 16 + g) * KSTR + kb;
                ah[mt][0] = *(const uint32_t*)&AsH[ro];
                ah[mt][1] = *(const uint32_t*)&AsH[ro + 8 * KSTR];
                ah[mt][2] = *(const uint32_t*)&AsH[ro + 8];
                ah[mt][3] = *(const uint32_t*)&AsH[ro + 8 * KSTR + 8];
                al[mt][0] = *(const uint32_t*)&AsL[ro];
                al[mt][1] = *(const uint32_t*)&AsL[ro + 8 * KSTR];
                al[mt][2] = *(const uint32_t*)&AsL[ro + 8];
                al[mt][3] = *(const uint32_t*)&AsL[ro + 8 * KSTR + 8];
            }
#pragma unroll
            for (int nt = 0; nt < 4; nt++) {
                const int ro = (wn + nt * 8 + g) * KSTR + kb;
                bh[nt][0] = *(const uint32_t*)&BsH[ro];
                bh[nt][1] = *(const uint32_t*)&BsH[ro + 8];
                bl[nt][0] = *(const uint32_t*)&BsL[ro];
                bl[nt][1] = *(const uint32_t*)&BsL[ro + 8];
            }
            // term-outer order: each acc revisited only after 15 indep MMAs
#pragma unroll
            for (int mt = 0; mt < 4; mt++)
#pragma unroll
                for (int nt = 0; nt < 4; nt++)
                    mma_bf16(acc[mt][nt], ah[mt][0], ah[mt][1], ah[mt][2], ah[mt][3],
                             bl[nt][0], bl[nt][1]);
#pragma unroll
            for (int mt = 0; mt < 4; mt++)
#pragma unroll
                for (int nt = 0; nt < 4; nt++)
                    mma_bf16(acc[mt][nt], al[mt][0], al[mt][1], al[mt][2], al[mt][3],
                             bh[nt][0], bh[nt][1]);
#pragma unroll
            for (int mt = 0; mt < 4; mt++)
#pragma unroll
                for (int nt = 0; nt < 4; nt++)
                    mma_bf16(acc[mt][nt], ah[mt][0], ah[mt][1], ah[mt][2], ah[mt][3],
                             bh[nt][0], bh[nt][1]);
        }
        __syncthreads();
    }

    // ----- epilogue -----
#pragma unroll
    for (int mt = 0; mt < 4; mt++) {
#pragma unroll
        for (int half = 0; half < 2; half++) {
            const int m = m0 + wm + mt * 16 + g + half * 8;
            if (MODE == 0) {
                const int b = m / NTOK;
                const int n = m - b * NTOK;
#pragma unroll
                for (int nt = 0; nt < 4; nt++) {
                    const int col0 = n0 + wn + nt * 8 + 2 * t;
                    float v0 = acc[mt][nt][half * 2 + 0] + bias[col0];
                    float v1 = acc[mt][nt][half * 2 + 1] + bias[col0 + 1];
                    const int which = col0 / DIM;
                    const int rem   = col0 - which * DIM;
                    const int h     = rem >> 6;
                    const int dd    = rem & 63;
                    const int bhI   = b * NH + h;
                    if (which == 0) {
                        float2 q2 = make_float2(v0 * 0.125f, v1 * 0.125f);
                        *(float2*)&g_q[((size_t)bhI * NTOK + n) * HD + dd] = q2;
                    } else if (which == 1) {
                        uint32_t hp, lp;
                        pack_hl(v0, v1, hp, lp);
                        const size_t idx = ((size_t)bhI * NPAD + n) * HD + dd;
                        *(uint32_t*)&g_kH[idx] = hp;
                        *(uint32_t*)&g_kL[idx] = lp;
                    } else {
                        const size_t i0 = ((size_t)bhI * HD + dd) * NPAD + n;
                        __nv_bfloat16 h0 = __float2bfloat16(v0);
                        __nv_bfloat16 h1 = __float2bfloat16(v1);
                        g_vH[i0]        = h0;
                        g_vH[i0 + NPAD] = h1;
                        g_vL[i0]        = __float2bfloat16(v0 - __bfloat162float(h0));
                        g_vL[i0 + NPAD] = __float2bfloat16(v1 - __bfloat162float(h1));
                    }
                }
            } else {
#pragma unroll
                for (int nt = 0; nt < 4; nt++) {
                    const int col = n0 + wn + nt * 8 + 2 * t;
                    float2 v;
                    v.x = acc[mt][nt][half * 2 + 0] + bias[col];
                    v.y = acc[mt][nt][half * 2 + 1] + bias[col + 1];
                    *(float2*)&out[(size_t)m * DIM + col] = v;
                }
            }
        }
    }
}

// =========================================================================
// Tensor-core flash attention (round 8 structure, term-outer MMA order).
// =========================================================================
#define KS_STR  72
#define KV_TILE (64*KS_STR*2)
#define KV_STAGE (4*KV_TILE)
#define SRH_OFF 0
#define SRW_OFF (SRH_OFF + REL*HD*4)
#define SBH_OFF (SRW_OFF + REL*HD*4)
#define SBW_OFF (SBH_OFF + 208*14*4)
#define SKV_OFF (SBW_OFF + 208*14*4)
#define ATT_SMEM (SKV_OFF + 2*KV_STAGE)           // 110848 B

#define ATHR 416

__global__ __launch_bounds__(ATHR, 1) void attn_mma(const float* __restrict__ relh,
                                                    const float* __restrict__ relw)
{
    extern __shared__ char smc[];
    float* RH = (float*)(smc + SRH_OFF);
    float* RW = (float*)(smc + SRW_OFF);
    float* BH = (float*)(smc + SBH_OFF);
    float* BW = (float*)(smc + SBW_OFF);

    const int bh  = blockIdx.x;
    const int tid = threadIdx.x;
    const int w    = tid >> 5;
    const int lane = tid & 31;
    const int g    = lane >> 2;
    const int t    = lane & 3;

    const float* qg = g_q + (size_t)bh * NTOK * HD;
    const uint32_t kvbase = (uint32_t)__cvta_generic_to_shared(smc + SKV_OFF);

#define PREFETCH_CHUNK(j0, s)                                              \
    {                                                                      \
        for (int idx = tid; idx < 2048; idx += ATHR) {                     \
            const int tile = idx >> 9;                                     \
            const int r    = (idx >> 3) & 63;                              \
            const int c8   = idx & 7;                                      \
            const __nv_bfloat16* src;                                      \
            if (tile == 0)      src = g_kH + ((size_t)bh * NPAD + (j0) + r) * HD + c8 * 8; \
            else if (tile == 1) src = g_kL + ((size_t)bh * NPAD + (j0) + r) * HD + c8 * 8; \
            else if (tile == 2) src = g_vH + ((size_t)bh * HD + r) * NPAD + (j0) + c8 * 8; \
            else                src = g_vL + ((size_t)bh * HD + r) * NPAD + (j0) + c8 * 8; \
            cp16(kvbase + (s) * KV_STAGE + tile * KV_TILE + r * (KS_STR*2) + c8 * 16, src); \
        }                                                                  \
        CP_COMMIT();                                                       \
    }

    PREFETCH_CHUNK(0, 0);

    for (int idx = tid; idx < REL * HD / 4; idx += ATHR) {
        ((float4*)RH)[idx] = ((const float4*)relh)[idx];
        ((float4*)RW)[idx] = ((const float4*)relw)[idx];
    }
    __syncthreads();

    if (tid < NTOK) {
        float4 q4[16];
        const float4* qr = (const float4*)(qg + tid * HD);
#pragma unroll
        for (int i = 0; i < 16; i++) q4[i] = qr[i];
        const int qh = tid / WIN, qw = tid - qh * WIN;
#pragma unroll 1
        for (int kk = 0; kk < WIN; kk++) {
            const float4* rh4 = (const float4*)(RH + (qh - kk + WIN - 1) * HD);
            const float4* rw4 = (const float4*)(RW + (qw - kk + WIN - 1) * HD);
            float sh = 0.f, sw = 0.f;
#pragma unroll
            for (int i = 0; i < 16; i++) {
                float4 a = q4[i], r = rh4[i], wv = rw4[i];
                sh += a.x * r.x + a.y * r.y + a.z * r.z + a.w * r.w;
                sw += a.x * wv.x + a.y * wv.y + a.z * wv.z + a.w * wv.w;
            }
            BH[tid * WIN + kk] = sh;
            BW[tid * WIN + kk] = sw;
        }
    } else if (tid < 208) {
#pragma unroll
        for (int kk = 0; kk < WIN; kk++) {
            BH[tid * WIN + kk] = 0.f;
            BW[tid * WIN + kk] = 0.f;
        }
    }

    const int r0 = w * 16 + g;
    const int r1 = r0 + 8;
    const int rq0 = (r0 < NTOK) ? r0 : NTOK - 1;
    const int rq1 = (r1 < NTOK) ? r1 : NTOK - 1;
    uint32_t qfh[4][4], qfl[4][4];
#pragma unroll
    for (int kt = 0; kt < 4; kt++) {
        const int kc = kt * 16 + 2 * t;
        float2 v0 = *(const float2*)(qg + rq0 * HD + kc);
        float2 v1 = *(const float2*)(qg + rq1 * HD + kc);
        float2 v2 = *(const float2*)(qg + rq0 * HD + kc + 8);
        float2 v3 = *(const float2*)(qg + rq1 * HD + kc + 8);
        pack_hl(v0.x, v0.y, qfh[kt][0], qfl[kt][0]);
        pack_hl(v1.x, v1.y, qfh[kt][1], qfl[kt][1]);
        pack_hl(v2.x, v2.y, qfh[kt][2], qfl[kt][2]);
        pack_hl(v3.x, v3.y, qfh[kt][3], qfl[kt][3]);
    }

    float oacc[8][4];
#pragma unroll
    for (int j = 0; j < 8; j++)
#pragma unroll
        for (int r = 0; r < 4; r++) oacc[j][r] = 0.f;
    float lsum0 = 0.f, lsum1 = 0.f;

#pragma unroll 1
    for (int chunk = 0; chunk < 4; chunk++) {
        const int j0 = chunk * 64;
        const int s  = chunk & 1;
        CP_WAIT(0);
        __syncthreads();
        if (chunk < 3) PREFETCH_CHUNK(j0 + 64, s ^ 1);

        const __nv_bfloat16* KH = (const __nv_bfloat16*)(smc + SKV_OFF + s * KV_STAGE);
        const __nv_bfloat16* KL = KH + 64 * KS_STR;
        const __nv_bfloat16* VH = KH + 2 * 64 * KS_STR;
        const __nv_bfloat16* VL = KH + 3 * 64 * KS_STR;

        float sacc[8][4];
#pragma unroll
        for (int j = 0; j < 8; j++)
#pragma unroll
            for (int r = 0; r < 4; r++) sacc[j][r] = 0.f;

#pragma unroll
        for (int kt = 0; kt < 4; kt++) {
            const int kc = kt * 16 + 2 * t;
            uint32_t kh0[8], kh1[8], kl0[8], kl1[8];
#pragma unroll
            for (int nt = 0; nt < 8; nt++) {
                const int krow = (nt * 8 + g) * KS_STR + kc;
                kh0[nt] = *(const uint32_t*)&KH[krow];
                kh1[nt] = *(const uint32_t*)&KH[krow + 8];
                kl0[nt] = *(const uint32_t*)&KL[krow];
                kl1[nt] = *(const uint32_t*)&KL[krow + 8];
            }
            // term-outer order over 8 independent sacc tiles
#pragma unroll
            for (int nt = 0; nt < 8; nt++)
                mma_bf16(sacc[nt], qfh[kt][0], qfh[kt][1], qfh[kt][2], qfh[kt][3],
                         kl0[nt], kl1[nt]);
#pragma unroll
            for (int nt = 0; nt < 8; nt++)
                mma_bf16(sacc[nt], qfl[kt][0], qfl[kt][1], qfl[kt][2], qfl[kt][3],
                         kh0[nt], kh1[nt]);
#pragma unroll
            for (int nt = 0; nt < 8; nt++)
                mma_bf16(sacc[nt], qfh[kt][0], qfh[kt][1], qfh[kt][2], qfh[kt][3],
                         kh0[nt], kh1[nt]);
        }

#pragma unroll
        for (int nt = 0; nt < 8; nt++) {
#pragma unroll
            for (int e = 0; e < 2; e++) {
                const int c = j0 + nt * 8 + 2 * t + e;
                float p0 = 0.f, p1 = 0.f;
                if (c < NTOK) {
                    const int kh = c / WIN;
                    const int kw = c - kh * WIN;
                    p0 = __expf(sacc[nt][e]     + BH[r0 * WIN + kh] + BW[r0 * WIN + kw]);
                    p1 = __expf(sacc[nt][2 + e] + BH[r1 * WIN + kh] + BW[r1 * WIN + kw]);
                }
                sacc[nt][e]     = p0;
                sacc[nt][2 + e] = p1;
                lsum0 += p0;
                lsum1 += p1;
            }
        }

#pragma unroll
        for (int kt = 0; kt < 4; kt++) {
            uint32_t ph[4], pl[4];
            pack_hl(sacc[2*kt][0],   sacc[2*kt][1],   ph[0], pl[0]);
            pack_hl(sacc[2*kt][2],   sacc[2*kt][3],   ph[1], pl[1]);
            pack_hl(sacc[2*kt+1][0], sacc[2*kt+1][1], ph[2], pl[2]);
            pack_hl(sacc[2*kt+1][2], sacc[2*kt+1][3], ph[3], pl[3]);
            const int kc = kt * 16 + 2 * t;
            uint32_t vh0[8], vh1[8], vl0[8], vl1[8];
#pragma unroll
            for (int nt = 0; nt < 8; nt++) {
                const int vrow = (nt * 8 + g) * KS_STR + kc;
                vh0[nt] = *(const uint32_t*)&VH[vrow];
                vh1[nt] = *(const uint32_t*)&VH[vrow + 8];
                vl0[nt] = *(const uint32_t*)&VL[vrow];
                vl1[nt] = *(const uint32_t*)&VL[vrow + 8];
            }
#pragma unroll
            for (int nt = 0; nt < 8; nt++)
                mma_bf16(oacc[nt], ph[0], ph[1], ph[2], ph[3], vl0[nt], vl1[nt]);
#pragma unroll
            for (int nt = 0; nt < 8; nt++)
                mma_bf16(oacc[nt], pl[0], pl[1], pl[2], pl[3], vh0[nt], vh1[nt]);
#pragma unroll
            for (int nt = 0; nt < 8; nt++)
                mma_bf16(oacc[nt], ph[0], ph[1], ph[2], ph[3], vh0[nt], vh1[nt]);
        }
    }

    lsum0 += __shfl_xor_sync(0xffffffff, lsum0, 1);
    lsum0 += __shfl_xor_sync(0xffffffff, lsum0, 2);
    lsum1 += __shfl_xor_sync(0xffffffff, lsum1, 1);
    lsum1 += __shfl_xor_sync(0xffffffff, lsum1, 2);

    const int b = bh / NH, h = bh - (bh / NH) * NH;
    const float inv0 = 1.f / lsum0;
    const float inv1 = 1.f / lsum1;
    if (r0 < NTOK) {
        const size_t off = ((size_t)b * NTOK + r0) * DIM + h * HD;
#pragma unroll
        for (int nt = 0; nt < 8; nt++) {
            uint32_t hp, lp;
            pack_hl(oacc[nt][0] * inv0, oacc[nt][1] * inv0, hp, lp);
            *(uint32_t*)&g_aoH[off + nt * 8 + 2 * t] = hp;
            *(uint32_t*)&g_aoL[off + nt * 8 + 2 * t] = lp;
        }
    }
    if (r1 < NTOK) {
        const size_t off = ((size_t)b * NTOK + r1) * DIM + h * HD;
#pragma unroll
        for (int nt = 0; nt < 8; nt++) {
            uint32_t hp, lp;
            pack_hl(oacc[nt][2] * inv1, oacc[nt][3] * inv1, hp, lp);
            *(uint32_t*)&g_aoH[off + nt * 8 + 2 * t] = hp;
            *(uint32_t*)&g_aoL[off + nt * 8 + 2 * t] = lp;
        }
    }
}

// =========================================================================
extern "C" void kernel_launch(void* const* d_in, const int* in_sizes, int n_in,
                              void* d_out, int out_size)
{
    const float* x      = (const float*)d_in[0];
    const float* qkv_w  = (const float*)d_in[1];
    const float* qkv_b  = (const float*)d_in[2];
    const float* relh   = (const float*)d_in[3];
    const float* relw   = (const float*)d_in[4];
    const float* proj_w = (const float*)d_in[5];
    const float* proj_b = (const float*)d_in[6];
    float* out = (float*)d_out;

    cudaFuncSetAttribute(attn_mma,
                         cudaFuncAttributeMaxDynamicSharedMemorySize, ATT_SMEM);

    // 0) one-shot bf16 hi/lo splits
    {
        const int n2x = MTOT * DIM / 2;
        split_kernel<0><<<(n2x + 255) / 256, 256>>>(x, n2x);
        const int n2q = 3 * DIM * DIM / 2;
        split_kernel<1><<<(n2q + 255) / 256, 256>>>(qkv_w, n2q);
        const int n2p = DIM * DIM / 2;
        split_kernel<2><<<(n2p + 255) / 256, 256>>>(proj_w, n2p);
    }

    // 1) QKV GEMM -> g_q (fp32), g_k hi/lo, g_v hi/lo transposed
    gemm_mma<0><<<dim3(2304 / 128, MTOT / 128), 256>>>(qkv_b, nullptr);

    // 2) tensor-core flash attention per (b, head) -> g_aoH/g_aoL
    attn_mma<<<BATCH * NH, ATHR, ATT_SMEM>>>(relh, relw);

    // 3) proj GEMM -> d_out
    gemm_mma<1><<<dim3(DIM / 128, MTOT / 128), 256>>>(proj_b, out);
}

// round 11
// speedup vs baseline: 1.3592x; 1.3592x over previous
#include <cuda_runtime.h>
#include <cuda_fp16.h>
#include <cstdint>

// ---------------- problem constants ----------------
#define BATCH   256
#define NH      12
#define HD      64
#define DIM     768          // NH*HD
#define WIN     14
#define NTOK    196          // WIN*WIN
#define NPAD    256          // padded token count for K/V tiles
#define MTOT    (BATCH*NTOK) // 50176
#define REL     27           // 2*WIN-1

// ---------------- scratch (device globals; no allocation allowed) -------
__device__ float g_q[BATCH*NH*NTOK*HD];                      // fp32, q*0.125
__device__ __half g_kH[BATCH*NH*NPAD*HD], g_kL[BATCH*NH*NPAD*HD]; // [b][h][n][d] hi/lo
__device__ __half g_vH[BATCH*NH*HD*NPAD], g_vL[BATCH*NH*HD*NPAD]; // [b][h][d][n] hi/lo
__device__ __half g_xF[MTOT*DIM];                            // x single fp16
__device__ __half g_wqH[3*DIM*DIM], g_wqL[3*DIM*DIM];        // qkv_w hi/lo
__device__ __half g_wpH[DIM*DIM],  g_wpL[DIM*DIM];           // proj_w hi/lo
__device__ __half g_aoF[MTOT*DIM];                           // attn out single fp16

// =========================================================================
// helpers
// =========================================================================
__device__ __forceinline__ void mma_f16(float c[4],
                                        uint32_t a0, uint32_t a1, uint32_t a2, uint32_t a3,
                                        uint32_t b0, uint32_t b1)
{
    asm("mma.sync.aligned.m16n8k16.row.col.f32.f16.f16.f32 "
        "{%0,%1,%2,%3}, {%4,%5,%6,%7}, {%8,%9}, {%0,%1,%2,%3};"
        : "+f"(c[0]), "+f"(c[1]), "+f"(c[2]), "+f"(c[3])
        : "r"(a0), "r"(a1), "r"(a2), "r"(a3), "r"(b0), "r"(b1));
}

__device__ __forceinline__ uint32_t pack_f16(float x0, float x1)
{
    uint32_t h;
    asm("cvt.rn.f16x2.f32 %0, %1, %2;" : "=r"(h) : "f"(x1), "f"(x0));
    return h;
}

// (x0,x1) -> f16x2 hi + f16x2 residual lo
__device__ __forceinline__ void pack_hl16(float x0, float x1, uint32_t& hi, uint32_t& lo)
{
    uint32_t h;
    asm("cvt.rn.f16x2.f32 %0, %1, %2;" : "=r"(h) : "f"(x1), "f"(x0));
    __half2 hh = *reinterpret_cast<__half2*>(&h);
    float h0 = __low2float(hh);
    float h1 = __high2float(hh);
    uint32_t l;
    asm("cvt.rn.f16x2.f32 %0, %1, %2;" : "=r"(l) : "f"(x1 - h1), "f"(x0 - h0));
    hi = h; lo = l;
}

__device__ __forceinline__ void cp16(uint32_t dst, const void* src)
{
    asm volatile("cp.async.cg.shared.global [%0], [%1], 16;" :: "r"(dst), "l"(src));
}
#define CP_COMMIT() asm volatile("cp.async.commit_group;")
#define CP_WAIT(n)  asm volatile("cp.async.wait_group %0;" :: "n"(n))

// =========================================================================
// one-shot split kernels: WHICH 0 -> x single fp16; 1/2 -> hi/lo weights
// =========================================================================
template<int WHICH>
__global__ __launch_bounds__(256) void split_kernel(const float* __restrict__ src, int n2)
{
    const int i = blockIdx.x * 256 + threadIdx.x;
    if (i >= n2) return;
    float2 v = ((const float2*)src)[i];
    if (WHICH == 0) {
        ((uint32_t*)g_xF)[i] = pack_f16(v.x, v.y);
    } else {
        uint32_t h, l;
        pack_hl16(v.x, v.y, h, l);
        if (WHICH == 1) { ((uint32_t*)g_wqH)[i] = h; ((uint32_t*)g_wqL)[i] = l; }
        else            { ((uint32_t*)g_wpH)[i] = h; ((uint32_t*)g_wpL)[i] = l; }
    }
}

// =========================================================================
// fp16 2-term GEMM: A single fp16, B hi/lo. reg-prefetch, round-9 order.
// CTA tile 128x128, BK=32, 256 threads = 8 warps (2M x 4N), warp 64x32.
// =========================================================================
#define KSTR 40                       // fp16 smem row stride

template<int MODE>
__global__ __launch_bounds__(256) void gemm_mma(const float* __restrict__ bias,
                                                float* __restrict__ out)
{
    __shared__ __half AsF[128 * KSTR];
    __shared__ __half BsH[128 * KSTR];
    __shared__ __half BsL[128 * KSTR];

    const int tid = threadIdx.x;
    const int m0  = blockIdx.y * 128;
    const int n0  = blockIdx.x * 128;

    const int w    = tid >> 5;
    const int lane = tid & 31;
    const int g    = lane >> 2;
    const int t    = lane & 3;
    const int wm   = (w >> 2) * 64;
    const int wn   = (w & 3) * 32;

    const int lr = tid >> 2;          // 0..63
    const int lc = (tid & 3) * 8;     // fp16 col 0,8,16,24

    const __half* gA  = (MODE ? g_aoF : g_xF) + (size_t)(m0 + lr) * 768 + lc;
    const __half* gBH = (MODE ? g_wpH : g_wqH) + (size_t)(n0 + lr) * 768 + lc;
    const __half* gBL = (MODE ? g_wpL : g_wqL) + (size_t)(n0 + lr) * 768 + lc;
    const size_t rstep = (size_t)64 * 768;

    float acc[4][4][4];
#pragma unroll
    for (int i = 0; i < 4; i++)
#pragma unroll
        for (int j = 0; j < 4; j++)
#pragma unroll
            for (int r = 0; r < 4; r++) acc[i][j][r] = 0.f;

    uint4 pa[2], pbh[2], pbl[2];
    pa[0]  = *(const uint4*)(gA);           pa[1]  = *(const uint4*)(gA + rstep);
    pbh[0] = *(const uint4*)(gBH);          pbh[1] = *(const uint4*)(gBH + rstep);
    pbl[0] = *(const uint4*)(gBL);          pbl[1] = *(const uint4*)(gBL + rstep);

    for (int k0 = 0; k0 < 768; k0 += 32) {
#pragma unroll
        for (int i = 0; i < 2; i++) {
            const int ro = (lr + i * 64) * KSTR + lc;
            *(uint4*)&AsF[ro] = pa[i];
            *(uint4*)&BsH[ro] = pbh[i];
            *(uint4*)&BsL[ro] = pbl[i];
        }
        __syncthreads();

        if (k0 + 32 < 768) {
            const int k1 = k0 + 32;
            pa[0]  = *(const uint4*)(gA + k1);           pa[1]  = *(const uint4*)(gA + k1 + rstep);
            pbh[0] = *(const uint4*)(gBH + k1);          pbh[1] = *(const uint4*)(gBH + k1 + rstep);
            pbl[0] = *(const uint4*)(gBL + k1);          pbl[1] = *(const uint4*)(gBL + k1 + rstep);
        }

#pragma unroll
        for (int ks = 0; ks < 2; ks++) {
            const int kb = ks * 16 + 2 * t;
            uint32_t a[4][4], bh[4][2], bl[4][2];
#pragma unroll
            for (int mt = 0; mt < 4; mt++) {
                const int ro = (wm + mt * 16 + g) * KSTR + kb;
                a[mt][0] = *(const uint32_t*)&AsF[ro];
                a[mt][1] = *(const uint32_t*)&AsF[ro + 8 * KSTR];
                a[mt][2] = *(const uint32_t*)&AsF[ro + 8];
                a[mt][3] = *(const uint32_t*)&AsF[ro + 8 * KSTR + 8];
            }
#pragma unroll
            for (int nt = 0; nt < 4; nt++) {
                const int ro = (wn + nt * 8 + g) * KSTR + kb;
                bh[nt][0] = *(const uint32_t*)&BsH[ro];
                bh[nt][1] = *(const uint32_t*)&BsH[ro + 8];
                bl[nt][0] = *(const uint32_t*)&BsL[ro];
                bl[nt][1] = *(const uint32_t*)&BsL[ro + 8];
            }
#pragma unroll
            for (int mt = 0; mt < 4; mt++)
#pragma unroll
                for (int nt = 0; nt < 4; nt++) {
                    mma_f16(acc[mt][nt], a[mt][0], a[mt][1], a[mt][2], a[mt][3],
                            bl[nt][0], bl[nt][1]);
                    mma_f16(acc[mt][nt], a[mt][0], a[mt][1], a[mt][2], a[mt][3],
                            bh[nt][0], bh[nt][1]);
                }
        }
        __syncthreads();
    }

    // ----- epilogue -----
#pragma unroll
    for (int mt = 0; mt < 4; mt++) {
#pragma unroll
        for (int half = 0; half < 2; half++) {
            const int m = m0 + wm + mt * 16 + g + half * 8;
            if (MODE == 0) {
                const int b = m / NTOK;
                const int n = m - b * NTOK;
#pragma unroll
                for (int nt = 0; nt < 4; nt++) {
                    const int col0 = n0 + wn + nt * 8 + 2 * t;
                    float v0 = acc[mt][nt][half * 2 + 0] + bias[col0];
                    float v1 = acc[mt][nt][half * 2 + 1] + bias[col0 + 1];
                    const int which = col0 / DIM;
                    const int rem   = col0 - which * DIM;
                    const int h     = rem >> 6;
                    const int dd    = rem & 63;
                    const int bhI   = b * NH + h;
                    if (which == 0) {
                        float2 q2 = make_float2(v0 * 0.125f, v1 * 0.125f);
                        *(float2*)&g_q[((size_t)bhI * NTOK + n) * HD + dd] = q2;
                    } else if (which == 1) {
                        uint32_t hp, lp;
                        pack_hl16(v0, v1, hp, lp);
                        const size_t idx = ((size_t)bhI * NPAD + n) * HD + dd;
                        *(uint32_t*)&g_kH[idx] = hp;
                        *(uint32_t*)&g_kL[idx] = lp;
                    } else { // V transposed [d][n], hi/lo
                        const size_t i0 = ((size_t)bhI * HD + dd) * NPAD + n;
                        __half h0 = __float2half_rn(v0);
                        __half h1 = __float2half_rn(v1);
                        g_vH[i0]        = h0;
                        g_vH[i0 + NPAD] = h1;
                        g_vL[i0]        = __float2half_rn(v0 - __half2float(h0));
                        g_vL[i0 + NPAD] = __float2half_rn(v1 - __half2float(h1));
                    }
                }
            } else {
#pragma unroll
                for (int nt = 0; nt < 4; nt++) {
                    const int col = n0 + wn + nt * 8 + 2 * t;
                    float2 v;
                    v.x = acc[mt][nt][half * 2 + 0] + bias[col];
                    v.y = acc[mt][nt][half * 2 + 1] + bias[col + 1];
                    *(float2*)&out[(size_t)m * DIM + col] = v;
                }
            }
        }
    }
}

// =========================================================================
// Tensor-core flash attention: Q single fp16, K hi/lo, P single, V hi/lo.
// One CTA per (b,h), 416 threads = 13 warps, cp.async double buffer.
// =========================================================================
#define KS_STR  72
#define KV_TILE (64*KS_STR*2)
#define KV_STAGE (4*KV_TILE)
#define SRH_OFF 0
#define SRW_OFF (SRH_OFF + REL*HD*4)
#define SBH_OFF (SRW_OFF + REL*HD*4)
#define SBW_OFF (SBH_OFF + 208*14*4)
#define SKV_OFF (SBW_OFF + 208*14*4)
#define ATT_SMEM (SKV_OFF + 2*KV_STAGE)           // 110848 B

#define ATHR 416

__global__ __launch_bounds__(ATHR, 1) void attn_mma(const float* __restrict__ relh,
                                                    const float* __restrict__ relw)
{
    extern __shared__ char smc[];
    float* RH = (float*)(smc + SRH_OFF);
    float* RW = (float*)(smc + SRW_OFF);
    float* BH = (float*)(smc + SBH_OFF);
    float* BW = (float*)(smc + SBW_OFF);

    const int bh  = blockIdx.x;
    const int tid = threadIdx.x;
    const int w    = tid >> 5;
    const int lane = tid & 31;
    const int g    = lane >> 2;
    const int t    = lane & 3;

    const float* qg = g_q + (size_t)bh * NTOK * HD;
    const uint32_t kvbase = (uint32_t)__cvta_generic_to_shared(smc + SKV_OFF);

#define PREFETCH_CHUNK(j0, s)                                              \
    {                                                                      \
        for (int idx = tid; idx < 2048; idx += ATHR) {                     \
            const int tile = idx >> 9;                                     \
            const int r    = (idx >> 3) & 63;                              \
            const int c8   = idx & 7;                                      \
            const __half* src;                                             \
            if (tile == 0)      src = g_kH + ((size_t)bh * NPAD + (j0) + r) * HD + c8 * 8; \
            else if (tile == 1) src = g_kL + ((size_t)bh * NPAD + (j0) + r) * HD + c8 * 8; \
            else if (tile == 2) src = g_vH + ((size_t)bh * HD + r) * NPAD + (j0) + c8 * 8; \
            else                src = g_vL + ((size_t)bh * HD + r) * NPAD + (j0) + c8 * 8; \
            cp16(kvbase + (s) * KV_STAGE + tile * KV_TILE + r * (KS_STR*2) + c8 * 16, src); \
        }                                                                  \
        CP_COMMIT();                                                       \
    }

    PREFETCH_CHUNK(0, 0);

    for (int idx = tid; idx < REL * HD / 4; idx += ATHR) {
        ((float4*)RH)[idx] = ((const float4*)relh)[idx];
        ((float4*)RW)[idx] = ((const float4*)relw)[idx];
    }
    __syncthreads();

    if (tid < NTOK) {
        float4 q4[16];
        const float4* qr = (const float4*)(qg + tid * HD);
#pragma unroll
        for (int i = 0; i < 16; i++) q4[i] = qr[i];
        const int qh = tid / WIN, qw = tid - qh * WIN;
#pragma unroll 1
        for (int kk = 0; kk < WIN; kk++) {
            const float4* rh4 = (const float4*)(RH + (qh - kk + WIN - 1) * HD);
            const float4* rw4 = (const float4*)(RW + (qw - kk + WIN - 1) * HD);
            float sh = 0.f, sw = 0.f;
#pragma unroll
            for (int i = 0; i < 16; i++) {
                float4 a = q4[i], r = rh4[i], wv = rw4[i];
                sh += a.x * r.x + a.y * r.y + a.z * r.z + a.w * r.w;
                sw += a.x * wv.x + a.y * wv.y + a.z * wv.z + a.w * wv.w;
            }
            BH[tid * WIN + kk] = sh;
            BW[tid * WIN + kk] = sw;
        }
    } else if (tid < 208) {
#pragma unroll
        for (int kk = 0; kk < WIN; kk++) {
            BH[tid * WIN + kk] = 0.f;
            BW[tid * WIN + kk] = 0.f;
        }
    }

    // Q fragments: single fp16
    const int r0 = w * 16 + g;
    const int r1 = r0 + 8;
    const int rq0 = (r0 < NTOK) ? r0 : NTOK - 1;
    const int rq1 = (r1 < NTOK) ? r1 : NTOK - 1;
    uint32_t qf[4][4];
#pragma unroll
    for (int kt = 0; kt < 4; kt++) {
        const int kc = kt * 16 + 2 * t;
        float2 v0 = *(const float2*)(qg + rq0 * HD + kc);
        float2 v1 = *(const float2*)(qg + rq1 * HD + kc);
        float2 v2 = *(const float2*)(qg + rq0 * HD + kc + 8);
        float2 v3 = *(const float2*)(qg + rq1 * HD + kc + 8);
        qf[kt][0] = pack_f16(v0.x, v0.y);
        qf[kt][1] = pack_f16(v1.x, v1.y);
        qf[kt][2] = pack_f16(v2.x, v2.y);
        qf[kt][3] = pack_f16(v3.x, v3.y);
    }

    float oacc[8][4];
#pragma unroll
    for (int j = 0; j < 8; j++)
#pragma unroll
        for (int r = 0; r < 4; r++) oacc[j][r] = 0.f;
    float lsum0 = 0.f, lsum1 = 0.f;

#pragma unroll 1
    for (int chunk = 0; chunk < 4; chunk++) {
        const int j0 = chunk * 64;
        const int s  = chunk & 1;
        CP_WAIT(0);
        __syncthreads();
        if (chunk < 3) PREFETCH_CHUNK(j0 + 64, s ^ 1);

        const __half* KH = (const __half*)(smc + SKV_OFF + s * KV_STAGE);
        const __half* KL = KH + 64 * KS_STR;
        const __half* VH = KH + 2 * 64 * KS_STR;
        const __half* VL = KH + 3 * 64 * KS_STR;

        float sacc[8][4];
#pragma unroll
        for (int j = 0; j < 8; j++)
#pragma unroll
            for (int r = 0; r < 4; r++) sacc[j][r] = 0.f;

#pragma unroll
        for (int kt = 0; kt < 4; kt++) {
            const int kc = kt * 16 + 2 * t;
#pragma unroll
            for (int nt = 0; nt < 8; nt++) {
                const int krow = (nt * 8 + g) * KS_STR + kc;
                uint32_t kh0 = *(const uint32_t*)&KH[krow];
                uint32_t kh1 = *(const uint32_t*)&KH[krow + 8];
                uint32_t kl0 = *(const uint32_t*)&KL[krow];
                uint32_t kl1 = *(const uint32_t*)&KL[krow + 8];
                mma_f16(sacc[nt], qf[kt][0], qf[kt][1], qf[kt][2], qf[kt][3], kl0, kl1);
                mma_f16(sacc[nt], qf[kt][0], qf[kt][1], qf[kt][2], qf[kt][3], kh0, kh1);
            }
        }

#pragma unroll
        for (int nt = 0; nt < 8; nt++) {
#pragma unroll
            for (int e = 0; e < 2; e++) {
                const int c = j0 + nt * 8 + 2 * t + e;
                float p0 = 0.f, p1 = 0.f;
                if (c < NTOK) {
                    const int kh = c / WIN;
                    const int kw = c - kh * WIN;
                    p0 = __expf(sacc[nt][e]     + BH[r0 * WIN + kh] + BW[r0 * WIN + kw]);
                    p1 = __expf(sacc[nt][2 + e] + BH[r1 * WIN + kh] + BW[r1 * WIN + kw]);
                }
                sacc[nt][e]     = p0;
                sacc[nt][2 + e] = p1;
                lsum0 += p0;
                lsum1 += p1;
            }
        }

#pragma unroll
        for (int kt = 0; kt < 4; kt++) {
            uint32_t ph[4];
            ph[0] = pack_f16(sacc[2*kt][0],   sacc[2*kt][1]);
            ph[1] = pack_f16(sacc[2*kt][2],   sacc[2*kt][3]);
            ph[2] = pack_f16(sacc[2*kt+1][0], sacc[2*kt+1][1]);
            ph[3] = pack_f16(sacc[2*kt+1][2], sacc[2*kt+1][3]);
            const int kc = kt * 16 + 2 * t;
#pragma unroll
            for (int nt = 0; nt < 8; nt++) {
                const int vrow = (nt * 8 + g) * KS_STR + kc;
                uint32_t vh0 = *(const uint32_t*)&VH[vrow];
                uint32_t vh1 = *(const uint32_t*)&VH[vrow + 8];
                uint32_t vl0 = *(const uint32_t*)&VL[vrow];
                uint32_t vl1 = *(const uint32_t*)&VL[vrow + 8];
                mma_f16(oacc[nt], ph[0], ph[1], ph[2], ph[3], vl0, vl1);
                mma_f16(oacc[nt], ph[0], ph[1], ph[2], ph[3], vh0, vh1);
            }
        }
    }

    lsum0 += __shfl_xor_sync(0xffffffff, lsum0, 1);
    lsum0 += __shfl_xor_sync(0xffffffff, lsum0, 2);
    lsum1 += __shfl_xor_sync(0xffffffff, lsum1, 1);
    lsum1 += __shfl_xor_sync(0xffffffff, lsum1, 2);

    const int b = bh / NH, h = bh - (bh / NH) * NH;
    const float inv0 = 1.f / lsum0;
    const float inv1 = 1.f / lsum1;
    if (r0 < NTOK) {
        const size_t off = ((size_t)b * NTOK + r0) * DIM + h * HD;
#pragma unroll
        for (int nt = 0; nt < 8; nt++)
            *(uint32_t*)&g_aoF[off + nt * 8 + 2 * t] =
                pack_f16(oacc[nt][0] * inv0, oacc[nt][1] * inv0);
    }
    if (r1 < NTOK) {
        const size_t off = ((size_t)b * NTOK + r1) * DIM + h * HD;
#pragma unroll
        for (int nt = 0; nt < 8; nt++)
            *(uint32_t*)&g_aoF[off + nt * 8 + 2 * t] =
                pack_f16(oacc[nt][2] * inv1, oacc[nt][3] * inv1);
    }
}

// =========================================================================
extern "C" void kernel_launch(void* const* d_in, const int* in_sizes, int n_in,
                              void* d_out, int out_size)
{
    const float* x      = (const float*)d_in[0];
    const float* qkv_w  = (const float*)d_in[1];
    const float* qkv_b  = (const float*)d_in[2];
    const float* relh   = (const float*)d_in[3];
    const float* relw   = (const float*)d_in[4];
    const float* proj_w = (const float*)d_in[5];
    const float* proj_b = (const float*)d_in[6];
    float* out = (float*)d_out;

    cudaFuncSetAttribute(attn_mma,
                         cudaFuncAttributeMaxDynamicSharedMemorySize, ATT_SMEM);

    // 0) one-shot fp16 splits
    {
        const int n2x = MTOT * DIM / 2;
        split_kernel<0><<<(n2x + 255) / 256, 256>>>(x, n2x);
        const int n2q = 3 * DIM * DIM / 2;
        split_kernel<1><<<(n2q + 255) / 256, 256>>>(qkv_w, n2q);
        const int n2p = DIM * DIM / 2;
        split_kernel<2><<<(n2p + 255) / 256, 256>>>(proj_w, n2p);
    }

    // 1) QKV GEMM -> g_q (fp32), g_k hi/lo, g_v hi/lo transposed
    gemm_mma<0><<<dim3(2304 / 128, MTOT / 128), 256>>>(qkv_b, nullptr);

    // 2) tensor-core flash attention per (b, head) -> g_aoF
    attn_mma<<<BATCH * NH, ATHR, ATT_SMEM>>>(relh, relw);

    // 3) proj GEMM -> d_out
    gemm_mma<1><<<dim3(DIM / 128, MTOT / 128), 256>>>(proj_b, out);
}